// round 9
// baseline (speedup 1.0000x reference)
#include <cuda_runtime.h>
#include <cstdint>

#define NNODES 50000
#define EMAX   800000
#define DFEAT  128

// ---- scratch (device globals: no allocation allowed) ----
__device__ __align__(256) float  g_H[NNODES * DFEAT];   // h = (1+eps)*x + agg
__device__ __align__(256) float  g_Z1[NNODES * DFEAT];  // pre-BN output of linear1
__device__ __align__(256) double g_stats[512];          // sum1,sq1,sum2,sq2 (128 each)
__device__ int g_deg[NNODES];                           // per-node in-degree
__device__ int g_off[NNODES + 1];                       // CSR offsets
__device__ int g_cur[NNODES];                           // fill cursors
__device__ int g_srcs[EMAX];                            // src ids grouped by dst
__device__ int g_is64;                                  // edge_index dtype flag

__device__ __forceinline__ uint32_t to_tf32(float x) {
    uint32_t r;
    asm("cvt.rna.tf32.f32 %0, %1;" : "=r"(r) : "f"(x));
    return r;
}

// ============================ prep: zero deg/stats + dtype probe ============================
__global__ void prep_kernel(const void* eiv, int E, int N) {
    int idx = blockIdx.x * blockDim.x + threadIdx.x;
    if (idx < N) g_deg[idx] = 0;
    if (idx < 512) g_stats[idx] = 0.0;
    if (blockIdx.x == 0) {
        __shared__ int bad;
        if (threadIdx.x == 0) bad = 0;
        __syncthreads();
        const long long* p = (const long long*)eiv;
        int n = E < 1024 ? E : 1024;
        for (int i = threadIdx.x; i < n; i += blockDim.x) {
            long long v = p[i];
            if (v < 0 || v >= (long long)N) atomicOr(&bad, 1);
        }
        __syncthreads();
        if (threadIdx.x == 0) g_is64 = bad ? 0 : 1;
    }
}

// ============================ CSR build ============================
__global__ void hist_kernel(const void* __restrict__ eiv, int E) {
    int e = blockIdx.x * blockDim.x + threadIdx.x;
    if (e >= E) return;
    int d = g_is64 ? (int)((const long long*)eiv)[E + e] : ((const int*)eiv)[E + e];
    atomicAdd(&g_deg[d], 1);
}

// single-block exclusive scan over g_deg -> g_off, g_cur (1024 threads)
__global__ void scan_kernel(int N) {
    __shared__ int ssum[1024];
    int t = threadIdx.x;
    int chunk = (N + 1023) / 1024;
    int lo = t * chunk, hi = lo + chunk;
    if (hi > N) hi = N;
    int s = 0;
    for (int i = lo; i < hi; i++) s += g_deg[i];
    ssum[t] = s;
    __syncthreads();
    for (int o = 1; o < 1024; o <<= 1) {
        int v = (t >= o) ? ssum[t - o] : 0;
        __syncthreads();
        ssum[t] += v;
        __syncthreads();
    }
    int run = ssum[t] - s;   // exclusive base for this chunk
    for (int i = lo; i < hi; i++) {
        g_off[i] = run;
        g_cur[i] = run;
        run += g_deg[i];
    }
    if (t == 1023) g_off[N] = ssum[1023];
}

__global__ void fill_kernel(const void* __restrict__ eiv, int E) {
    int e = blockIdx.x * blockDim.x + threadIdx.x;
    if (e >= E) return;
    int s, d;
    if (g_is64) {
        const long long* ei = (const long long*)eiv;
        s = (int)ei[e]; d = (int)ei[E + e];
    } else {
        const int* ei = (const int*)eiv;
        s = ei[e]; d = ei[E + e];
    }
    int pos = atomicAdd(&g_cur[d], 1);
    g_srcs[pos] = s;
}

// ============================ gather: h[i] = (1+eps)x[i] + sum_j x[srcs(i,j)] ============================
__global__ void __launch_bounds__(256) gather_kernel(const float* __restrict__ x,
                                                     const float* __restrict__ epsp, int N) {
    int warp = (blockIdx.x * blockDim.x + threadIdx.x) >> 5;
    if (warp >= N) return;
    int lane = threadIdx.x & 31;
    float cep = 1.0f + __ldg(epsp);
    float4 xv = __ldg(((const float4*)x) + (size_t)warp * 32 + lane);
    float4 acc = make_float4(xv.x * cep, xv.y * cep, xv.z * cep, xv.w * cep);
    int lo = g_off[warp], hi = g_off[warp + 1];
    int j = lo;
    for (; j + 4 <= hi; j += 4) {
        int s0 = g_srcs[j], s1 = g_srcs[j + 1], s2 = g_srcs[j + 2], s3 = g_srcs[j + 3];
        float4 v0 = __ldg(((const float4*)x) + (size_t)s0 * 32 + lane);
        float4 v1 = __ldg(((const float4*)x) + (size_t)s1 * 32 + lane);
        float4 v2 = __ldg(((const float4*)x) + (size_t)s2 * 32 + lane);
        float4 v3 = __ldg(((const float4*)x) + (size_t)s3 * 32 + lane);
        acc.x += (v0.x + v1.x) + (v2.x + v3.x);
        acc.y += (v0.y + v1.y) + (v2.y + v3.y);
        acc.z += (v0.z + v1.z) + (v2.z + v3.z);
        acc.w += (v0.w + v1.w) + (v2.w + v3.w);
    }
    for (; j < hi; j++) {
        int s = g_srcs[j];
        float4 v = __ldg(((const float4*)x) + (size_t)s * 32 + lane);
        acc.x += v.x; acc.y += v.y; acc.z += v.z; acc.w += v.w;
    }
    ((float4*)g_H)[(size_t)warp * 32 + lane] = acc;
}

// ---- legacy fallback path (only if E > EMAX or N > NNODES never expected) ----
__global__ void init_h_kernel(const float* __restrict__ x, const float* __restrict__ eps, int n4) {
    int idx = blockIdx.x * blockDim.x + threadIdx.x;
    if (idx >= n4) return;
    float c = 1.0f + *eps;
    float4 v = ((const float4*)x)[idx];
    v.x *= c; v.y *= c; v.z *= c; v.w *= c;
    ((float4*)g_H)[idx] = v;
}
__global__ void __launch_bounds__(256) scatter_kernel(const float* __restrict__ x,
                                                      const void* __restrict__ eiv, int E) {
    int lane = threadIdx.x & 31;
    int warp = (blockIdx.x * blockDim.x + threadIdx.x) >> 5;
    for (int e = warp * 8; e < warp * 8 + 8 && e < E; e++) {
        long long s, d;
        if (g_is64) {
            const long long* ei = (const long long*)eiv;
            s = __ldg(&ei[e]); d = __ldg(&ei[E + e]);
        } else {
            const int* ei = (const int*)eiv;
            s = __ldg(&ei[e]); d = __ldg(&ei[E + e]);
        }
        float4 v = __ldg(((const float4*)(x + s * 128)) + lane);
        float* dp = g_H + d * 128 + (lane << 2);
        asm volatile("red.global.add.v4.f32 [%0], {%1,%2,%3,%4};"
                     :: "l"(dp), "f"(v.x), "f"(v.y), "f"(v.z), "f"(v.w) : "memory");
    }
}

// ============================ tf32 mma.sync GEMM ============================
// Z[m][n] = bias[n] + sum_k f(A[m][k]) * W[n][k]
// MODE 0: A=g_H,  f=identity,                          Z=g_Z1
// MODE 1: A=g_Z1, f=relu(bn1(.)), bn1 computed inline, Z=Zout
// Block: 128x128 tile, K=128 in smem (stride 132, conflict-free frags).
// 512 threads = 16 warps in 4(m) x 4(n); warp tile 32x32; mma.m16n8k8.tf32.
// Register double-buffered fragments; column sum/sumsq fused in epilogue.
#define MMA_SMEM_FLOATS (640 + 2 * 128 * 132)
#define MMA_SMEM_BYTES  (MMA_SMEM_FLOATS * 4)

__device__ __forceinline__ void mma_tf32_16n8k8(float c[4], const uint32_t a[4],
                                                uint32_t b0, uint32_t b1) {
    asm volatile(
        "mma.sync.aligned.m16n8k8.row.col.f32.tf32.tf32.f32 "
        "{%0,%1,%2,%3}, {%4,%5,%6,%7}, {%8,%9}, {%0,%1,%2,%3};"
        : "+f"(c[0]), "+f"(c[1]), "+f"(c[2]), "+f"(c[3])
        : "r"(a[0]), "r"(a[1]), "r"(a[2]), "r"(a[3]), "r"(b0), "r"(b1));
}

template <int MODE>
__global__ void __launch_bounds__(512) mma_gemm(const float* __restrict__ Wmat,
                                                const float* __restrict__ bias,
                                                const float* __restrict__ gamma,
                                                const float* __restrict__ beta,
                                                float* __restrict__ Zout, int M) {
    extern __shared__ float sm[];
    float* s_bias  = sm;
    float* s_scale = sm + 128;
    float* s_shift = sm + 256;
    float* s_sum   = sm + 384;
    float* s_sq    = sm + 512;
    float* As      = sm + 640;             // [128][132] (tf32 bits)
    float* Bs      = As + 128 * 132;       // [128][132] (tf32 bits), [n][k]
    const uint32_t* As32 = (const uint32_t*)As;
    const uint32_t* Bs32 = (const uint32_t*)Bs;

    const float* A = MODE ? g_Z1 : g_H;
    float* Z       = MODE ? Zout : g_Z1;

    int tid = threadIdx.x;
    int m0 = blockIdx.x * 128;

    if (tid < 128) {
        s_bias[tid] = bias[tid];
        s_sum[tid] = 0.f;
        s_sq[tid]  = 0.f;
        if (MODE) {
            // inline finalize of BN1 from g_stats (redundant per block, trivial)
            double mean = g_stats[tid] / (double)M;
            double var  = g_stats[128 + tid] / (double)M - mean * mean;
            float sc = gamma[tid] * rsqrtf((float)var + 1e-5f);
            s_scale[tid] = sc;
            s_shift[tid] = beta[tid] - (float)mean * sc;
        }
    }
    __syncthreads();

    // load B (=W, [n][k] natural layout), tf32-rounded (4096 float4)
#pragma unroll
    for (int i = 0; i < 8; i++) {
        int idx = i * 512 + tid;
        int n = idx >> 5, k4 = idx & 31;
        float4 v = __ldg(((const float4*)Wmat) + idx);
        uint32_t* dst = (uint32_t*)(Bs + n * 132 + k4 * 4);
        dst[0] = to_tf32(v.x); dst[1] = to_tf32(v.y);
        dst[2] = to_tf32(v.z); dst[3] = to_tf32(v.w);
    }
    // load A tile (fused bn1+relu in MODE 1), tf32-rounded
#pragma unroll
    for (int i = 0; i < 8; i++) {
        int idx = i * 512 + tid;
        int m = idx >> 5, k4 = idx & 31;
        int gm = m0 + m;
        float4 v = make_float4(0.f, 0.f, 0.f, 0.f);
        if (gm < M) v = __ldg(((const float4*)A) + (size_t)gm * 32 + k4);
        if (MODE) {
            int k = k4 * 4;
            v.x = fmaxf(fmaf(v.x, s_scale[k + 0], s_shift[k + 0]), 0.f);
            v.y = fmaxf(fmaf(v.y, s_scale[k + 1], s_shift[k + 1]), 0.f);
            v.z = fmaxf(fmaf(v.z, s_scale[k + 2], s_shift[k + 2]), 0.f);
            v.w = fmaxf(fmaf(v.w, s_scale[k + 3], s_shift[k + 3]), 0.f);
        }
        uint32_t* dst = (uint32_t*)(As + m * 132 + k4 * 4);
        dst[0] = to_tf32(v.x); dst[1] = to_tf32(v.y);
        dst[2] = to_tf32(v.z); dst[3] = to_tf32(v.w);
    }
    __syncthreads();

    int lane = tid & 31;
    int wid  = tid >> 5;                   // 0..15
    int g = lane >> 2, t = lane & 3;
    int wm = wid >> 2;                     // 0..3
    int wn = wid & 3;                      // 0..3
    int arow = wm * 32;
    int bcol = wn * 32;

    float acc[2][4][4];
#pragma unroll
    for (int mt = 0; mt < 2; mt++)
#pragma unroll
        for (int nt = 0; nt < 4; nt++)
#pragma unroll
            for (int q = 0; q < 4; q++) acc[mt][nt][q] = 0.f;

    uint32_t a[2][2][4];
    uint32_t b[2][4][2];

#define LOAD_FRAG(ks, buf)                                                   \
    do {                                                                     \
        int _k0 = (ks) * 8;                                                  \
        _Pragma("unroll")                                                    \
        for (int mt = 0; mt < 2; mt++) {                                     \
            int rb = arow + mt * 16;                                         \
            a[buf][mt][0] = As32[(rb + g) * 132 + _k0 + t];                  \
            a[buf][mt][1] = As32[(rb + g + 8) * 132 + _k0 + t];              \
            a[buf][mt][2] = As32[(rb + g) * 132 + _k0 + t + 4];              \
            a[buf][mt][3] = As32[(rb + g + 8) * 132 + _k0 + t + 4];          \
        }                                                                    \
        _Pragma("unroll")                                                    \
        for (int nt = 0; nt < 4; nt++) {                                     \
            b[buf][nt][0] = Bs32[(bcol + nt * 8 + g) * 132 + _k0 + t];       \
            b[buf][nt][1] = Bs32[(bcol + nt * 8 + g) * 132 + _k0 + t + 4];   \
        }                                                                    \
    } while (0)

    LOAD_FRAG(0, 0);
#pragma unroll
    for (int ks = 0; ks < 16; ks++) {
        int cur = ks & 1;
        if (ks < 15) LOAD_FRAG(ks + 1, cur ^ 1);
#pragma unroll
        for (int nt = 0; nt < 4; nt++) {
            mma_tf32_16n8k8(acc[0][nt], a[cur][0], b[cur][nt][0], b[cur][nt][1]);
            mma_tf32_16n8k8(acc[1][nt], a[cur][1], b[cur][nt][0], b[cur][nt][1]);
        }
    }
#undef LOAD_FRAG

    // epilogue: bias add, store float2 pairs, fused column stats
#pragma unroll
    for (int nt = 0; nt < 4; nt++) {
        int col = bcol + nt * 8 + 2 * t;
        float bi0 = s_bias[col], bi1 = s_bias[col + 1];
        float cs0 = 0.f, cq0 = 0.f, cs1 = 0.f, cq1 = 0.f;
#pragma unroll
        for (int mt = 0; mt < 2; mt++) {
#pragma unroll
            for (int rr = 0; rr < 2; rr++) {
                int gm = m0 + arow + mt * 16 + g + rr * 8;
                if (gm < M) {
                    float o0 = acc[mt][nt][rr * 2 + 0] + bi0;
                    float o1 = acc[mt][nt][rr * 2 + 1] + bi1;
                    *(float2*)(Z + (size_t)gm * 128 + col) = make_float2(o0, o1);
                    cs0 += o0; cq0 += o0 * o0;
                    cs1 += o1; cq1 += o1 * o1;
                }
            }
        }
        atomicAdd(&s_sum[col], cs0);     atomicAdd(&s_sq[col], cq0);
        atomicAdd(&s_sum[col + 1], cs1); atomicAdd(&s_sq[col + 1], cq1);
    }
    __syncthreads();
    if (tid < 128) {
        double* sum = g_stats + (MODE ? 256 : 0);
        double* sq  = g_stats + (MODE ? 384 : 128);
        atomicAdd(&sum[tid], (double)s_sum[tid]);
        atomicAdd(&sq[tid],  (double)s_sq[tid]);
    }
}

// ---- final: out = relu(bn2(out)) in place; BN2 finalize inlined per block ----
__global__ void bn_relu_out_kernel(float* __restrict__ out,
                                   const float* __restrict__ gamma,
                                   const float* __restrict__ beta,
                                   int M, int n4) {
    __shared__ float sc[128], sh[128];
    int t = threadIdx.x;
    if (t < 128) {
        double mean = g_stats[256 + t] / (double)M;
        double var  = g_stats[384 + t] / (double)M - mean * mean;
        float s = gamma[t] * rsqrtf((float)var + 1e-5f);
        sc[t] = s;
        sh[t] = beta[t] - (float)mean * s;
    }
    __syncthreads();
    int idx = blockIdx.x * blockDim.x + t;
    if (idx >= n4) return;
    float4 v = ((float4*)out)[idx];
    int k = (idx & 31) * 4;
    v.x = fmaxf(fmaf(v.x, sc[k + 0], sh[k + 0]), 0.f);
    v.y = fmaxf(fmaf(v.y, sc[k + 1], sh[k + 1]), 0.f);
    v.z = fmaxf(fmaf(v.z, sc[k + 2], sh[k + 2]), 0.f);
    v.w = fmaxf(fmaf(v.w, sc[k + 3], sh[k + 3]), 0.f);
    ((float4*)out)[idx] = v;
}

extern "C" void kernel_launch(void* const* d_in, const int* in_sizes, int n_in,
                              void* d_out, int out_size) {
    const float* x   = (const float*)d_in[0];
    const void*  ei  = d_in[1];
    // d_in[2] = batch (unused; single graph, BN over all nodes)
    const float* eps = (const float*)d_in[3];
    const float* W1  = (const float*)d_in[4];
    const float* b1  = (const float*)d_in[5];
    const float* g1  = (const float*)d_in[6];
    const float* be1 = (const float*)d_in[7];
    const float* W2  = (const float*)d_in[8];
    const float* b2  = (const float*)d_in[9];
    const float* g2  = (const float*)d_in[10];
    const float* be2 = (const float*)d_in[11];
    float* out = (float*)d_out;

    int N = in_sizes[0] / 128;
    int E = in_sizes[1] / 2;
    int n4 = N * 32;

    cudaFuncSetAttribute(mma_gemm<0>, cudaFuncAttributeMaxDynamicSharedMemorySize, MMA_SMEM_BYTES);
    cudaFuncSetAttribute(mma_gemm<1>, cudaFuncAttributeMaxDynamicSharedMemorySize, MMA_SMEM_BYTES);

    prep_kernel<<<(N + 511) / 512, 512>>>(ei, E, N);
    if (E <= EMAX && N <= NNODES) {
        // CSR build + gather (no atomic reductions on feature rows)
        hist_kernel<<<(E + 255) / 256, 256>>>(ei, E);
        scan_kernel<<<1, 1024>>>(N);
        fill_kernel<<<(E + 255) / 256, 256>>>(ei, E);
        gather_kernel<<<(N * 32 + 255) / 256, 256>>>(x, eps, N);
    } else {
        // legacy fallback
        init_h_kernel<<<(n4 + 255) / 256, 256>>>(x, eps, n4);
        scatter_kernel<<<(E + 63) / 64, 256>>>(x, ei, E);
    }

    int gblocks = (N + 127) / 128;
    mma_gemm<0><<<gblocks, 512, MMA_SMEM_BYTES>>>(W1, b1, nullptr, nullptr, nullptr, N);
    mma_gemm<1><<<gblocks, 512, MMA_SMEM_BYTES>>>(W2, b2, g1, be1, out, N);
    bn_relu_out_kernel<<<(n4 + 255) / 256, 256>>>(out, g2, be2, N, n4);
}

// round 10
// speedup vs baseline: 1.1951x; 1.1951x over previous
#include <cuda_runtime.h>
#include <cstdint>

#define NNODES 50000
#define DFEAT 128

// ---- scratch (device globals: no allocation allowed) ----
__device__ __align__(256) float  g_H[NNODES * DFEAT];   // h = (1+eps)*x + agg
__device__ __align__(256) float  g_Z1[NNODES * DFEAT];  // pre-BN output of linear1
__device__ __align__(256) double g_stats[512];          // sum1,sq1,sum2,sq2 (128 each)
__device__ int g_is64;                                  // edge_index dtype flag

__device__ __forceinline__ uint32_t to_tf32(float x) {
    uint32_t r;
    asm("cvt.rna.tf32.f32 %0, %1;" : "=r"(r) : "f"(x));
    return r;
}

// ============================ small kernels ============================

// zero stats + probe edge dtype. One block, 512 threads.
__global__ void prep_kernel(const void* eiv, int E, int N) {
    int t = threadIdx.x;
    g_stats[t] = 0.0;
    __shared__ int bad;
    if (t == 0) bad = 0;
    __syncthreads();
    const long long* p = (const long long*)eiv;
    int n = E < 1024 ? E : 1024;
    for (int i = t; i < n; i += blockDim.x) {
        long long v = p[i];
        if (v < 0 || v >= (long long)N) atomicOr(&bad, 1);
    }
    __syncthreads();
    if (t == 0) g_is64 = bad ? 0 : 1;
}

// h = (1+eps) * x
__global__ void init_h_kernel(const float* __restrict__ x, const float* __restrict__ eps, int n4) {
    int idx = blockIdx.x * blockDim.x + threadIdx.x;
    if (idx >= n4) return;
    float c = 1.0f + *eps;
    float4 v = ((const float4*)x)[idx];
    v.x *= c; v.y *= c; v.z *= c; v.w *= c;
    ((float4*)g_H)[idx] = v;
}

// edge scatter-add: 8 edges per warp (MLP=8), vector L2 reductions
__global__ void __launch_bounds__(256) scatter_kernel(const float* __restrict__ x,
                                                      const void* __restrict__ eiv, int E) {
    int lane = threadIdx.x & 31;
    int warp = (blockIdx.x * blockDim.x + threadIdx.x) >> 5;
    int e0 = warp * 8;
    if (e0 >= E) return;
    int is64 = g_is64;

    if (e0 + 8 <= E) {
        long long s[8], d[8];
        if (is64) {
            const long long* ei = (const long long*)eiv;
#pragma unroll
            for (int k = 0; k < 8; k++) { s[k] = __ldg(&ei[e0 + k]); d[k] = __ldg(&ei[E + e0 + k]); }
        } else {
            const int* ei = (const int*)eiv;
#pragma unroll
            for (int k = 0; k < 8; k++) { s[k] = __ldg(&ei[e0 + k]); d[k] = __ldg(&ei[E + e0 + k]); }
        }
        float4 v[8];
#pragma unroll
        for (int k = 0; k < 8; k++)
            v[k] = __ldg(((const float4*)(x + s[k] * 128)) + lane);
#pragma unroll
        for (int k = 0; k < 8; k++) {
            float* dp = g_H + d[k] * 128 + (lane << 2);
            asm volatile("red.global.add.v4.f32 [%0], {%1,%2,%3,%4};"
                         :: "l"(dp), "f"(v[k].x), "f"(v[k].y), "f"(v[k].z), "f"(v[k].w) : "memory");
        }
    } else {
        for (int e = e0; e < E; e++) {
            long long s, d;
            if (is64) {
                const long long* ei = (const long long*)eiv;
                s = __ldg(&ei[e]); d = __ldg(&ei[E + e]);
            } else {
                const int* ei = (const int*)eiv;
                s = __ldg(&ei[e]); d = __ldg(&ei[E + e]);
            }
            float4 v = __ldg(((const float4*)(x + s * 128)) + lane);
            float* dp = g_H + d * 128 + (lane << 2);
            asm volatile("red.global.add.v4.f32 [%0], {%1,%2,%3,%4};"
                         :: "l"(dp), "f"(v.x), "f"(v.y), "f"(v.z), "f"(v.w) : "memory");
        }
    }
}

// ============================ tf32 mma.sync GEMM ============================
// Z[m][n] = bias[n] + sum_k f(A[m][k]) * W[n][k]
// MODE 0: A=g_H,  f=identity,                          Z=g_Z1
// MODE 1: A=g_Z1, f=relu(bn1(.)), bn1 finalized inline, Z=Zout
// Block: 128x128 tile, K=128 in smem (stride 132, conflict-free frags).
// 512 threads = 16 warps in 4(m) x 4(n); warp tile 32x32; mma.m16n8k8.tf32.
// Register double-buffered fragments; column sum/sumsq fused in epilogue.
#define MMA_SMEM_FLOATS (640 + 2 * 128 * 132)
#define MMA_SMEM_BYTES  (MMA_SMEM_FLOATS * 4)

__device__ __forceinline__ void mma_tf32_16n8k8(float c[4], const uint32_t a[4],
                                                uint32_t b0, uint32_t b1) {
    asm volatile(
        "mma.sync.aligned.m16n8k8.row.col.f32.tf32.tf32.f32 "
        "{%0,%1,%2,%3}, {%4,%5,%6,%7}, {%8,%9}, {%0,%1,%2,%3};"
        : "+f"(c[0]), "+f"(c[1]), "+f"(c[2]), "+f"(c[3])
        : "r"(a[0]), "r"(a[1]), "r"(a[2]), "r"(a[3]), "r"(b0), "r"(b1));
}

template <int MODE>
__global__ void __launch_bounds__(512) mma_gemm(const float* __restrict__ Wmat,
                                                const float* __restrict__ bias,
                                                const float* __restrict__ gamma,
                                                const float* __restrict__ beta,
                                                float* __restrict__ Zout, int M) {
    extern __shared__ float sm[];
    float* s_bias  = sm;
    float* s_scale = sm + 128;
    float* s_shift = sm + 256;
    float* s_sum   = sm + 384;
    float* s_sq    = sm + 512;
    float* As      = sm + 640;             // [128][132] (tf32 bits)
    float* Bs      = As + 128 * 132;       // [128][132] (tf32 bits), [n][k]
    const uint32_t* As32 = (const uint32_t*)As;
    const uint32_t* Bs32 = (const uint32_t*)Bs;

    const float* A = MODE ? g_Z1 : g_H;
    float* Z       = MODE ? Zout : g_Z1;

    int tid = threadIdx.x;
    int m0 = blockIdx.x * 128;

    if (tid < 128) {
        s_bias[tid] = bias[tid];
        s_sum[tid] = 0.f;
        s_sq[tid]  = 0.f;
        if (MODE) {
            // inline BN1 finalize from g_stats (redundant per block, trivial)
            double mean = g_stats[tid] / (double)M;
            double var  = g_stats[128 + tid] / (double)M - mean * mean;
            float sc = gamma[tid] * rsqrtf((float)var + 1e-5f);
            s_scale[tid] = sc;
            s_shift[tid] = beta[tid] - (float)mean * sc;
        }
    }
    __syncthreads();

    // load B (=W, [n][k] natural layout), tf32-rounded (4096 float4)
#pragma unroll
    for (int i = 0; i < 8; i++) {
        int idx = i * 512 + tid;
        int n = idx >> 5, k4 = idx & 31;
        float4 v = __ldg(((const float4*)Wmat) + idx);
        uint32_t* dst = (uint32_t*)(Bs + n * 132 + k4 * 4);
        dst[0] = to_tf32(v.x); dst[1] = to_tf32(v.y);
        dst[2] = to_tf32(v.z); dst[3] = to_tf32(v.w);
    }
    // load A tile (fused bn1+relu in MODE 1), tf32-rounded
#pragma unroll
    for (int i = 0; i < 8; i++) {
        int idx = i * 512 + tid;
        int m = idx >> 5, k4 = idx & 31;
        int gm = m0 + m;
        float4 v = make_float4(0.f, 0.f, 0.f, 0.f);
        if (gm < M) v = __ldg(((const float4*)A) + (size_t)gm * 32 + k4);
        if (MODE) {
            int k = k4 * 4;
            v.x = fmaxf(fmaf(v.x, s_scale[k + 0], s_shift[k + 0]), 0.f);
            v.y = fmaxf(fmaf(v.y, s_scale[k + 1], s_shift[k + 1]), 0.f);
            v.z = fmaxf(fmaf(v.z, s_scale[k + 2], s_shift[k + 2]), 0.f);
            v.w = fmaxf(fmaf(v.w, s_scale[k + 3], s_shift[k + 3]), 0.f);
        }
        uint32_t* dst = (uint32_t*)(As + m * 132 + k4 * 4);
        dst[0] = to_tf32(v.x); dst[1] = to_tf32(v.y);
        dst[2] = to_tf32(v.z); dst[3] = to_tf32(v.w);
    }
    __syncthreads();

    int lane = tid & 31;
    int wid  = tid >> 5;                   // 0..15
    int g = lane >> 2, t = lane & 3;
    int wm = wid >> 2;                     // 0..3
    int wn = wid & 3;                      // 0..3
    int arow = wm * 32;                    // warp's A row base (in tile)
    int bcol = wn * 32;                    // warp's B col base (in tile)

    float acc[2][4][4];
#pragma unroll
    for (int mt = 0; mt < 2; mt++)
#pragma unroll
        for (int nt = 0; nt < 4; nt++)
#pragma unroll
            for (int q = 0; q < 4; q++) acc[mt][nt][q] = 0.f;

    // double-buffered fragments
    uint32_t a[2][2][4];
    uint32_t b[2][4][2];

#define LOAD_FRAG(ks, buf)                                                   \
    do {                                                                     \
        int _k0 = (ks) * 8;                                                  \
        _Pragma("unroll")                                                    \
        for (int mt = 0; mt < 2; mt++) {                                     \
            int rb = arow + mt * 16;                                         \
            a[buf][mt][0] = As32[(rb + g) * 132 + _k0 + t];                  \
            a[buf][mt][1] = As32[(rb + g + 8) * 132 + _k0 + t];              \
            a[buf][mt][2] = As32[(rb + g) * 132 + _k0 + t + 4];              \
            a[buf][mt][3] = As32[(rb + g + 8) * 132 + _k0 + t + 4];          \
        }                                                                    \
        _Pragma("unroll")                                                    \
        for (int nt = 0; nt < 4; nt++) {                                     \
            b[buf][nt][0] = Bs32[(bcol + nt * 8 + g) * 132 + _k0 + t];       \
            b[buf][nt][1] = Bs32[(bcol + nt * 8 + g) * 132 + _k0 + t + 4];   \
        }                                                                    \
    } while (0)

    LOAD_FRAG(0, 0);
#pragma unroll
    for (int ks = 0; ks < 16; ks++) {
        int cur = ks & 1;
        if (ks < 15) LOAD_FRAG(ks + 1, cur ^ 1);
#pragma unroll
        for (int nt = 0; nt < 4; nt++) {
            mma_tf32_16n8k8(acc[0][nt], a[cur][0], b[cur][nt][0], b[cur][nt][1]);
            mma_tf32_16n8k8(acc[1][nt], a[cur][1], b[cur][nt][0], b[cur][nt][1]);
        }
    }
#undef LOAD_FRAG

    // epilogue: bias add, store float2 pairs, fused column stats
#pragma unroll
    for (int nt = 0; nt < 4; nt++) {
        int col = bcol + nt * 8 + 2 * t;
        float bi0 = s_bias[col], bi1 = s_bias[col + 1];
        float cs0 = 0.f, cq0 = 0.f, cs1 = 0.f, cq1 = 0.f;
#pragma unroll
        for (int mt = 0; mt < 2; mt++) {
#pragma unroll
            for (int rr = 0; rr < 2; rr++) {
                int gm = m0 + arow + mt * 16 + g + rr * 8;
                if (gm < M) {
                    float o0 = acc[mt][nt][rr * 2 + 0] + bi0;
                    float o1 = acc[mt][nt][rr * 2 + 1] + bi1;
                    *(float2*)(Z + (size_t)gm * 128 + col) = make_float2(o0, o1);
                    cs0 += o0; cq0 += o0 * o0;
                    cs1 += o1; cq1 += o1 * o1;
                }
            }
        }
        atomicAdd(&s_sum[col], cs0);     atomicAdd(&s_sq[col], cq0);
        atomicAdd(&s_sum[col + 1], cs1); atomicAdd(&s_sq[col + 1], cq1);
    }
    __syncthreads();
    if (tid < 128) {
        double* sum = g_stats + (MODE ? 256 : 0);
        double* sq  = g_stats + (MODE ? 384 : 128);
        atomicAdd(&sum[tid], (double)s_sum[tid]);
        atomicAdd(&sq[tid],  (double)s_sq[tid]);
    }
}

// ---- final: out = relu(bn2(out)) in place; BN2 finalize inlined per block ----
__global__ void bn_relu_out_kernel(float* __restrict__ out,
                                   const float* __restrict__ gamma,
                                   const float* __restrict__ beta,
                                   int M, int n4) {
    __shared__ float sc[128], sh[128];
    int t = threadIdx.x;
    if (t < 128) {
        double mean = g_stats[256 + t] / (double)M;
        double var  = g_stats[384 + t] / (double)M - mean * mean;
        float s = gamma[t] * rsqrtf((float)var + 1e-5f);
        sc[t] = s;
        sh[t] = beta[t] - (float)mean * s;
    }
    __syncthreads();
    int idx = blockIdx.x * blockDim.x + t;
    if (idx >= n4) return;
    float4 v = ((float4*)out)[idx];
    int k = (idx & 31) * 4;
    v.x = fmaxf(fmaf(v.x, sc[k + 0], sh[k + 0]), 0.f);
    v.y = fmaxf(fmaf(v.y, sc[k + 1], sh[k + 1]), 0.f);
    v.z = fmaxf(fmaf(v.z, sc[k + 2], sh[k + 2]), 0.f);
    v.w = fmaxf(fmaf(v.w, sc[k + 3], sh[k + 3]), 0.f);
    ((float4*)out)[idx] = v;
}

extern "C" void kernel_launch(void* const* d_in, const int* in_sizes, int n_in,
                              void* d_out, int out_size) {
    const float* x   = (const float*)d_in[0];
    const void*  ei  = d_in[1];
    // d_in[2] = batch (unused; single graph, BN over all nodes)
    const float* eps = (const float*)d_in[3];
    const float* W1  = (const float*)d_in[4];
    const float* b1  = (const float*)d_in[5];
    const float* g1  = (const float*)d_in[6];
    const float* be1 = (const float*)d_in[7];
    const float* W2  = (const float*)d_in[8];
    const float* b2  = (const float*)d_in[9];
    const float* g2  = (const float*)d_in[10];
    const float* be2 = (const float*)d_in[11];
    float* out = (float*)d_out;

    int N = in_sizes[0] / 128;
    int E = in_sizes[1] / 2;
    int n4 = N * 32;

    cudaFuncSetAttribute(mma_gemm<0>, cudaFuncAttributeMaxDynamicSharedMemorySize, MMA_SMEM_BYTES);
    cudaFuncSetAttribute(mma_gemm<1>, cudaFuncAttributeMaxDynamicSharedMemorySize, MMA_SMEM_BYTES);

    prep_kernel<<<1, 512>>>(ei, E, N);
    init_h_kernel<<<(n4 + 255) / 256, 256>>>(x, eps, n4);
    scatter_kernel<<<(E + 63) / 64, 256>>>(x, ei, E);

    int gblocks = (N + 127) / 128;
    mma_gemm<0><<<gblocks, 512, MMA_SMEM_BYTES>>>(W1, b1, nullptr, nullptr, nullptr, N);
    mma_gemm<1><<<gblocks, 512, MMA_SMEM_BYTES>>>(W2, b2, g1, be1, out, N);
    bn_relu_out_kernel<<<(n4 + 255) / 256, 256>>>(out, g2, be2, N, n4);
}

// round 11
// speedup vs baseline: 1.3145x; 1.0999x over previous
#include <cuda_runtime.h>
#include <cstdint>

#define NNODES 50000
#define DFEAT 128

// ---- scratch (device globals: no allocation allowed) ----
__device__ __align__(256) float  g_H[NNODES * DFEAT];   // h = (1+eps)*x + agg
__device__ __align__(256) float  g_Z1[NNODES * DFEAT];  // pre-BN output of linear1
__device__ __align__(256) double g_stats[512];          // sum1,sq1,sum2,sq2 (128 each)
__device__ int g_is64;                                  // edge_index dtype flag

__device__ __forceinline__ uint32_t to_tf32(float x) {
    uint32_t r;
    asm("cvt.rna.tf32.f32 %0, %1;" : "=r"(r) : "f"(x));
    return r;
}

// ============================ small kernels ============================

// zero stats + probe edge dtype. One block, 512 threads.
__global__ void prep_kernel(const void* eiv, int E, int N) {
    int t = threadIdx.x;
    g_stats[t] = 0.0;
    __shared__ int bad;
    if (t == 0) bad = 0;
    __syncthreads();
    const long long* p = (const long long*)eiv;
    int n = E < 1024 ? E : 1024;
    for (int i = t; i < n; i += blockDim.x) {
        long long v = p[i];
        if (v < 0 || v >= (long long)N) atomicOr(&bad, 1);
    }
    __syncthreads();
    if (t == 0) g_is64 = bad ? 0 : 1;
}

// h = (1+eps) * x
__global__ void init_h_kernel(const float* __restrict__ x, const float* __restrict__ eps, int n4) {
    int idx = blockIdx.x * blockDim.x + threadIdx.x;
    if (idx >= n4) return;
    float c = 1.0f + *eps;
    float4 v = ((const float4*)x)[idx];
    v.x *= c; v.y *= c; v.z *= c; v.w *= c;
    ((float4*)g_H)[idx] = v;
}

// edge scatter-add: 8 edges per warp (MLP=8), vector L2 reductions
__global__ void __launch_bounds__(256) scatter_kernel(const float* __restrict__ x,
                                                      const void* __restrict__ eiv, int E) {
    int lane = threadIdx.x & 31;
    int warp = (blockIdx.x * blockDim.x + threadIdx.x) >> 5;
    int e0 = warp * 8;
    if (e0 >= E) return;
    int is64 = g_is64;

    if (e0 + 8 <= E) {
        long long s[8], d[8];
        if (is64) {
            const long long* ei = (const long long*)eiv;
#pragma unroll
            for (int k = 0; k < 8; k++) { s[k] = __ldg(&ei[e0 + k]); d[k] = __ldg(&ei[E + e0 + k]); }
        } else {
            const int* ei = (const int*)eiv;
#pragma unroll
            for (int k = 0; k < 8; k++) { s[k] = __ldg(&ei[e0 + k]); d[k] = __ldg(&ei[E + e0 + k]); }
        }
        float4 v[8];
#pragma unroll
        for (int k = 0; k < 8; k++)
            v[k] = __ldg(((const float4*)(x + s[k] * 128)) + lane);
#pragma unroll
        for (int k = 0; k < 8; k++) {
            float* dp = g_H + d[k] * 128 + (lane << 2);
            asm volatile("red.global.add.v4.f32 [%0], {%1,%2,%3,%4};"
                         :: "l"(dp), "f"(v[k].x), "f"(v[k].y), "f"(v[k].z), "f"(v[k].w) : "memory");
        }
    } else {
        for (int e = e0; e < E; e++) {
            long long s, d;
            if (is64) {
                const long long* ei = (const long long*)eiv;
                s = __ldg(&ei[e]); d = __ldg(&ei[E + e]);
            } else {
                const int* ei = (const int*)eiv;
                s = __ldg(&ei[e]); d = __ldg(&ei[E + e]);
            }
            float4 v = __ldg(((const float4*)(x + s * 128)) + lane);
            float* dp = g_H + d * 128 + (lane << 2);
            asm volatile("red.global.add.v4.f32 [%0], {%1,%2,%3,%4};"
                         :: "l"(dp), "f"(v.x), "f"(v.y), "f"(v.z), "f"(v.w) : "memory");
        }
    }
}

// ============================ tf32 mma.sync GEMM ============================
// Z[m][n] = bias[n] + sum_k f(A[m][k]) * W[n][k]
// MODE 0: A=g_H,  f=identity,                          Z=g_Z1
// MODE 1: A=g_Z1, f=relu(bn1(.)), bn1 finalized inline, Z=Zout
// Block: 128x128 tile, K=128 in smem (stride 132, conflict-free frags).
// 512 threads = 16 warps in 4(m) x 4(n); warp tile 32x32; mma.m16n8k8.tf32.
// Register double-buffered fragments; column sum/sumsq fused in epilogue.
#define MMA_SMEM_FLOATS (640 + 2 * 128 * 132)
#define MMA_SMEM_BYTES  (MMA_SMEM_FLOATS * 4)

__device__ __forceinline__ void mma_tf32_16n8k8(float c[4], const uint32_t a[4],
                                                uint32_t b0, uint32_t b1) {
    asm volatile(
        "mma.sync.aligned.m16n8k8.row.col.f32.tf32.tf32.f32 "
        "{%0,%1,%2,%3}, {%4,%5,%6,%7}, {%8,%9}, {%0,%1,%2,%3};"
        : "+f"(c[0]), "+f"(c[1]), "+f"(c[2]), "+f"(c[3])
        : "r"(a[0]), "r"(a[1]), "r"(a[2]), "r"(a[3]), "r"(b0), "r"(b1));
}

template <int MODE>
__global__ void __launch_bounds__(512) mma_gemm(const float* __restrict__ Wmat,
                                                const float* __restrict__ bias,
                                                const float* __restrict__ gamma,
                                                const float* __restrict__ beta,
                                                float* __restrict__ Zout,
                                                double invM, int M) {
    extern __shared__ float sm[];
    float* s_bias  = sm;
    float* s_scale = sm + 128;
    float* s_shift = sm + 256;
    float* s_sum   = sm + 384;
    float* s_sq    = sm + 512;
    float* As      = sm + 640;             // [128][132] (tf32 bits)
    float* Bs      = As + 128 * 132;       // [128][132] (tf32 bits), [n][k]
    const uint32_t* As32 = (const uint32_t*)As;
    const uint32_t* Bs32 = (const uint32_t*)Bs;

    const float* A = MODE ? g_Z1 : g_H;
    float* Z       = MODE ? Zout : g_Z1;

    int tid = threadIdx.x;
    int m0 = blockIdx.x * 128;

    if (tid < 128) {
        s_bias[tid] = bias[tid];
        s_sum[tid] = 0.f;
        s_sq[tid]  = 0.f;
        if (MODE) {
            // inline BN1 finalize from g_stats (mul-only, invM precomputed on host)
            double mean = g_stats[tid] * invM;
            double var  = g_stats[128 + tid] * invM - mean * mean;
            float sc = gamma[tid] * rsqrtf((float)var + 1e-5f);
            s_scale[tid] = sc;
            s_shift[tid] = beta[tid] - (float)mean * sc;
        }
    }
    __syncthreads();

    // load B (=W, [n][k] natural layout), tf32-rounded (4096 float4)
#pragma unroll
    for (int i = 0; i < 8; i++) {
        int idx = i * 512 + tid;
        int n = idx >> 5, k4 = idx & 31;
        float4 v = __ldg(((const float4*)Wmat) + idx);
        uint32_t* dst = (uint32_t*)(Bs + n * 132 + k4 * 4);
        dst[0] = to_tf32(v.x); dst[1] = to_tf32(v.y);
        dst[2] = to_tf32(v.z); dst[3] = to_tf32(v.w);
    }
    // load A tile (fused bn1+relu in MODE 1), tf32-rounded
#pragma unroll
    for (int i = 0; i < 8; i++) {
        int idx = i * 512 + tid;
        int m = idx >> 5, k4 = idx & 31;
        int gm = m0 + m;
        float4 v = make_float4(0.f, 0.f, 0.f, 0.f);
        if (gm < M) v = __ldg(((const float4*)A) + (size_t)gm * 32 + k4);
        if (MODE) {
            int k = k4 * 4;
            v.x = fmaxf(fmaf(v.x, s_scale[k + 0], s_shift[k + 0]), 0.f);
            v.y = fmaxf(fmaf(v.y, s_scale[k + 1], s_shift[k + 1]), 0.f);
            v.z = fmaxf(fmaf(v.z, s_scale[k + 2], s_shift[k + 2]), 0.f);
            v.w = fmaxf(fmaf(v.w, s_scale[k + 3], s_shift[k + 3]), 0.f);
        }
        uint32_t* dst = (uint32_t*)(As + m * 132 + k4 * 4);
        dst[0] = to_tf32(v.x); dst[1] = to_tf32(v.y);
        dst[2] = to_tf32(v.z); dst[3] = to_tf32(v.w);
    }
    __syncthreads();

    int lane = tid & 31;
    int wid  = tid >> 5;                   // 0..15
    int g = lane >> 2, t = lane & 3;
    int wm = wid >> 2;                     // 0..3
    int wn = wid & 3;                      // 0..3
    int arow = wm * 32;                    // warp's A row base (in tile)
    int bcol = wn * 32;                    // warp's B col base (in tile)

    float acc[2][4][4];
#pragma unroll
    for (int mt = 0; mt < 2; mt++)
#pragma unroll
        for (int nt = 0; nt < 4; nt++)
#pragma unroll
            for (int q = 0; q < 4; q++) acc[mt][nt][q] = 0.f;

    // double-buffered fragments
    uint32_t a[2][2][4];
    uint32_t b[2][4][2];

#define LOAD_FRAG(ks, buf)                                                   \
    do {                                                                     \
        int _k0 = (ks) * 8;                                                  \
        _Pragma("unroll")                                                    \
        for (int mt = 0; mt < 2; mt++) {                                     \
            int rb = arow + mt * 16;                                         \
            a[buf][mt][0] = As32[(rb + g) * 132 + _k0 + t];                  \
            a[buf][mt][1] = As32[(rb + g + 8) * 132 + _k0 + t];              \
            a[buf][mt][2] = As32[(rb + g) * 132 + _k0 + t + 4];              \
            a[buf][mt][3] = As32[(rb + g + 8) * 132 + _k0 + t + 4];          \
        }                                                                    \
        _Pragma("unroll")                                                    \
        for (int nt = 0; nt < 4; nt++) {                                     \
            b[buf][nt][0] = Bs32[(bcol + nt * 8 + g) * 132 + _k0 + t];       \
            b[buf][nt][1] = Bs32[(bcol + nt * 8 + g) * 132 + _k0 + t + 4];   \
        }                                                                    \
    } while (0)

    LOAD_FRAG(0, 0);
#pragma unroll
    for (int ks = 0; ks < 16; ks++) {
        int cur = ks & 1;
        if (ks < 15) LOAD_FRAG(ks + 1, cur ^ 1);
#pragma unroll
        for (int nt = 0; nt < 4; nt++) {
            mma_tf32_16n8k8(acc[0][nt], a[cur][0], b[cur][nt][0], b[cur][nt][1]);
            mma_tf32_16n8k8(acc[1][nt], a[cur][1], b[cur][nt][0], b[cur][nt][1]);
        }
    }
#undef LOAD_FRAG

    // epilogue: bias add, store float2 pairs, fused column stats
#pragma unroll
    for (int nt = 0; nt < 4; nt++) {
        int col = bcol + nt * 8 + 2 * t;
        float bi0 = s_bias[col], bi1 = s_bias[col + 1];
        float cs0 = 0.f, cq0 = 0.f, cs1 = 0.f, cq1 = 0.f;
#pragma unroll
        for (int mt = 0; mt < 2; mt++) {
#pragma unroll
            for (int rr = 0; rr < 2; rr++) {
                int gm = m0 + arow + mt * 16 + g + rr * 8;
                if (gm < M) {
                    float o0 = acc[mt][nt][rr * 2 + 0] + bi0;
                    float o1 = acc[mt][nt][rr * 2 + 1] + bi1;
                    *(float2*)(Z + (size_t)gm * 128 + col) = make_float2(o0, o1);
                    cs0 += o0; cq0 += o0 * o0;
                    cs1 += o1; cq1 += o1 * o1;
                }
            }
        }
        atomicAdd(&s_sum[col], cs0);     atomicAdd(&s_sq[col], cq0);
        atomicAdd(&s_sum[col + 1], cs1); atomicAdd(&s_sq[col + 1], cq1);
    }
    __syncthreads();
    if (tid < 128) {
        double* sum = g_stats + (MODE ? 256 : 0);
        double* sq  = g_stats + (MODE ? 384 : 128);
        atomicAdd(&sum[tid], (double)s_sum[tid]);
        atomicAdd(&sq[tid],  (double)s_sq[tid]);
    }
}

// ---- final: out = relu(bn2(out)) in place; BN2 finalize inlined (mul-only),
//      grid-stride so only ~888 blocks recompute it ----
__global__ void bn_relu_out_kernel(float* __restrict__ out,
                                   const float* __restrict__ gamma,
                                   const float* __restrict__ beta,
                                   double invM, int n4) {
    __shared__ float sc[128], sh[128];
    int t = threadIdx.x;
    if (t < 128) {
        double mean = g_stats[256 + t] * invM;
        double var  = g_stats[384 + t] * invM - mean * mean;
        float s = gamma[t] * rsqrtf((float)var + 1e-5f);
        sc[t] = s;
        sh[t] = beta[t] - (float)mean * s;
    }
    __syncthreads();
    for (int idx = blockIdx.x * blockDim.x + t; idx < n4; idx += gridDim.x * blockDim.x) {
        float4 v = ((float4*)out)[idx];
        int k = (idx & 31) * 4;
        v.x = fmaxf(fmaf(v.x, sc[k + 0], sh[k + 0]), 0.f);
        v.y = fmaxf(fmaf(v.y, sc[k + 1], sh[k + 1]), 0.f);
        v.z = fmaxf(fmaf(v.z, sc[k + 2], sh[k + 2]), 0.f);
        v.w = fmaxf(fmaf(v.w, sc[k + 3], sh[k + 3]), 0.f);
        ((float4*)out)[idx] = v;
    }
}

extern "C" void kernel_launch(void* const* d_in, const int* in_sizes, int n_in,
                              void* d_out, int out_size) {
    const float* x   = (const float*)d_in[0];
    const void*  ei  = d_in[1];
    // d_in[2] = batch (unused; single graph, BN over all nodes)
    const float* eps = (const float*)d_in[3];
    const float* W1  = (const float*)d_in[4];
    const float* b1  = (const float*)d_in[5];
    const float* g1  = (const float*)d_in[6];
    const float* be1 = (const float*)d_in[7];
    const float* W2  = (const float*)d_in[8];
    const float* b2  = (const float*)d_in[9];
    const float* g2  = (const float*)d_in[10];
    const float* be2 = (const float*)d_in[11];
    float* out = (float*)d_out;

    int N = in_sizes[0] / 128;
    int E = in_sizes[1] / 2;
    int n4 = N * 32;
    double invM = 1.0 / (double)N;

    cudaFuncSetAttribute(mma_gemm<0>, cudaFuncAttributeMaxDynamicSharedMemorySize, MMA_SMEM_BYTES);
    cudaFuncSetAttribute(mma_gemm<1>, cudaFuncAttributeMaxDynamicSharedMemorySize, MMA_SMEM_BYTES);

    prep_kernel<<<1, 512>>>(ei, E, N);
    init_h_kernel<<<(n4 + 255) / 256, 256>>>(x, eps, n4);
    scatter_kernel<<<(E + 63) / 64, 256>>>(x, ei, E);

    int gblocks = (N + 127) / 128;
    mma_gemm<0><<<gblocks, 512, MMA_SMEM_BYTES>>>(W1, b1, nullptr, nullptr, nullptr, invM, N);
    mma_gemm<1><<<gblocks, 512, MMA_SMEM_BYTES>>>(W2, b2, g1, be1, out, invM, N);
    bn_relu_out_kernel<<<888, 256>>>(out, g2, be2, invM, n4);
}